// round 11
// baseline (speedup 1.0000x reference)
#include <cuda_runtime.h>
#include <cstdint>
#include <cmath>

#define NUM_ITEMS 40000
#define NIT 39999
#define D 300
#define DP 304
#define BB 64
#define LL 20
#define SS 5
#define NROWS 12800
#define SIMLD 40000

#define O_SCORES 1L
#define O_SUB    2559937L
#define O_COMP   40959937L
#define O_SESSMAP 79359937L

static __device__ float g_sim[(size_t)NROWS * SIMLD];
static __device__ float g_items[(size_t)NIT * DP];
static __device__ float g_samp[(size_t)NROWS * DP];
static __device__ float g_mapped[(size_t)NIT * D];
static __device__ float g_wt[(size_t)D * DP];
static __device__ float g_invnorm[NIT];
static __device__ float g_sess[BB * D];
static __device__ float g_red[BB];
static __device__ float g_M[NROWS];
static __device__ float g_Z[NROWS];

// ------------------------------------------------------------ XLA-CPU / Cephes exp replica
// Bit-exact replica of XLA:CPU's GenerateVF32Exp (llvm_ir_runtime.cc), which is
// the classic Eigen/Cephes pexp<float>. All ops forced to individual IEEE fp32
// roundings (no contraction) except where XLA emits fmuladd (the fx fma and the
// Horner steps, which lower to fused fma on aarch64 NEON).
__device__ __forceinline__ float exp_xla(float x) {
    x = fminf(x, 88.3762626647950f);
    x = fmaxf(x, -88.3762626647949f);
    float fx = floorf(__fmaf_rn(x, 1.44269504088896341f, 0.5f));
    float tmp = __fmul_rn(0.693359375f, fx);
    float z   = __fmul_rn(-2.12194440e-4f, fx);
    float r   = __fsub_rn(x, tmp);
    r = __fsub_rn(r, z);
    float zz = __fmul_rn(r, r);
    float y = __fmaf_rn(r, 1.9875691500E-4f, 1.3981999507E-3f);
    y = __fmaf_rn(y, r, 8.3334519073E-3f);
    y = __fmaf_rn(y, r, 4.1665795894E-2f);
    y = __fmaf_rn(y, r, 1.6666665459E-1f);
    y = __fmaf_rn(y, r, 5.0000001201E-1f);
    y = __fmaf_rn(y, zz, r);
    y = __fadd_rn(y, 1.0f);
    int emm0 = (((int)fx) + 127) << 23;
    return __fmul_rn(y, __int_as_float(emm0));
}

// ------------------------------------------------------------ prep
__global__ void k_prep_items(const float* __restrict__ emb) {
    int w = (blockIdx.x * blockDim.x + threadIdx.x) >> 5;
    int lane = threadIdx.x & 31;
    if (w >= NIT) return;
    const float* src = emb + (size_t)(w + 1) * D;
    float* dst = g_items + (size_t)w * DP;
    float ss = 0.f;
    for (int k = lane; k < DP; k += 32) {
        float v = (k < D) ? src[k] : 0.f;
        dst[k] = v;
        ss += v * v;
    }
    #pragma unroll
    for (int o = 16; o; o >>= 1) ss += __shfl_xor_sync(0xffffffffu, ss, o);
    if (lane == 0) g_invnorm[w] = 1.f / fmaxf(sqrtf(ss), 1e-12f);
}

__global__ void k_samp(const float* __restrict__ emb,
                       const int* __restrict__ viewed,
                       const int* __restrict__ bought) {
    int w = (blockIdx.x * blockDim.x + threadIdx.x) >> 5;
    int lane = threadIdx.x & 31;
    if (w >= NROWS) return;
    int idx = (w < NROWS / 2) ? viewed[w] : bought[w - NROWS / 2];
    const float* src = emb + (size_t)idx * D;
    float* dst = g_samp + (size_t)w * DP;
    for (int k = lane; k < DP; k += 32) dst[k] = (k < D) ? src[k] : 0.f;
}

__global__ void k_wt(const float* __restrict__ W) {
    int g = blockIdx.x * blockDim.x + threadIdx.x;
    if (g >= D * DP) return;
    int j = g / DP, d = g % DP;
    g_wt[g] = (d < D) ? W[d * D + j] : 0.f;
}

// ------------------------------------------------------------ SGEMM C = A * B^T
// K accumulated strictly sequentially (k ascending) with a single fp32 fma
// accumulator per output element — matches Eigen gebp dot order.
__global__ void __launch_bounds__(256, 2) sgemm_nt(
    const float* __restrict__ A, int lda,
    const float* __restrict__ Bm, int ldb,
    float* __restrict__ C, int ldc,
    int M, int N, int K)
{
    __shared__ float As[2][8][128];
    __shared__ float Bs[2][8][128];
    int tid = threadIdx.x;
    int bm = blockIdx.y << 7, bn = blockIdx.x << 7;
    int lrow = tid >> 1;
    int lk = (tid & 1) << 2;
    const float* Ap = A + (size_t)(bm + lrow) * lda + lk;
    const float* Bp = Bm + (size_t)(bn + lrow) * ldb + lk;
    bool avld = (bm + lrow) < M;
    bool bvld = (bn + lrow) < N;
    float4 za = make_float4(0.f, 0.f, 0.f, 0.f);
    float4 ra = avld ? *(const float4*)Ap : za;
    float4 rb = bvld ? *(const float4*)Bp : za;
    As[0][lk + 0][lrow] = ra.x; As[0][lk + 1][lrow] = ra.y;
    As[0][lk + 2][lrow] = ra.z; As[0][lk + 3][lrow] = ra.w;
    Bs[0][lk + 0][lrow] = rb.x; Bs[0][lk + 1][lrow] = rb.y;
    Bs[0][lk + 2][lrow] = rb.z; Bs[0][lk + 3][lrow] = rb.w;
    __syncthreads();
    float acc[8][8];
    #pragma unroll
    for (int i = 0; i < 8; i++)
        #pragma unroll
        for (int j = 0; j < 8; j++) acc[i][j] = 0.f;
    int ty = tid >> 4, tx = tid & 15;
    int buf = 0;
    for (int k0 = 8; k0 <= K; k0 += 8) {
        float4 na = za, nb = za;
        if (k0 < K) {
            na = avld ? *(const float4*)(Ap + k0) : za;
            nb = bvld ? *(const float4*)(Bp + k0) : za;
        }
        #pragma unroll
        for (int kk = 0; kk < 8; kk++) {
            float af[8], bf[8];
            *(float4*)(af)     = *(const float4*)(&As[buf][kk][ty << 3]);
            *(float4*)(af + 4) = *(const float4*)(&As[buf][kk][(ty << 3) + 4]);
            *(float4*)(bf)     = *(const float4*)(&Bs[buf][kk][tx << 3]);
            *(float4*)(bf + 4) = *(const float4*)(&Bs[buf][kk][(tx << 3) + 4]);
            #pragma unroll
            for (int i = 0; i < 8; i++)
                #pragma unroll
                for (int j = 0; j < 8; j++)
                    acc[i][j] = fmaf(af[i], bf[j], acc[i][j]);
        }
        if (k0 < K) {
            buf ^= 1;
            As[buf][lk + 0][lrow] = na.x; As[buf][lk + 1][lrow] = na.y;
            As[buf][lk + 2][lrow] = na.z; As[buf][lk + 3][lrow] = na.w;
            Bs[buf][lk + 0][lrow] = nb.x; Bs[buf][lk + 1][lrow] = nb.y;
            Bs[buf][lk + 2][lrow] = nb.z; Bs[buf][lk + 3][lrow] = nb.w;
            __syncthreads();
        }
    }
    #pragma unroll
    for (int i = 0; i < 8; i++) {
        int m = bm + (ty << 3) + i;
        if (m >= M) continue;
        float* crow = C + (size_t)m * ldc + bn + (tx << 3);
        int ncol = bn + (tx << 3);
        #pragma unroll
        for (int j = 0; j < 8; j++)
            if (ncol + j < N) crow[j] = acc[i][j];
    }
}

// ------------------------------------------------------------ session MLP
__global__ void __launch_bounds__(320) k_sess(
    const float* __restrict__ emb, const float* __restrict__ posw,
    const float* __restrict__ w1, const float* __restrict__ w2,
    const float* __restrict__ glu1w, const float* __restrict__ glu1b,
    const float* __restrict__ glu2w, const float* __restrict__ mapd,
    const int* __restrict__ inputs, const int* __restrict__ masks,
    float* __restrict__ out)
{
    __shared__ float h[LL * D];
    __shared__ float nh1[D];
    __shared__ float hs[D];
    __shared__ float g2[D];
    __shared__ float sessv[D];
    __shared__ float red[320];
    __shared__ float beta[LL];
    __shared__ float mm[LL];
    int b = blockIdx.x, tid = threadIdx.x;
    if (tid < LL) mm[tid] = (float)masks[b * LL + tid];
    __syncthreads();
    if (tid < D) {
        float cnt = 0.f;
        for (int l = 0; l < LL; l++) {
            int idx = inputs[b * LL + l];
            h[l * D + tid] = (idx == 0) ? 0.f : emb[(size_t)idx * D + tid];
            cnt += mm[l];
        }
        float acc = 0.f;
        for (int l = 0; l < LL; l++) acc = fmaf(mm[l], h[l * D + tid], acc);
        hs[tid] = acc / cnt;
    }
    __syncthreads();
    if (tid < D) {
        float g = 0.f;
        for (int d = 0; d < D; d++) g = fmaf(hs[d], glu2w[d * D + tid], g);
        g2[tid] = g;
    }
    __syncthreads();
    for (int l = 0; l < LL; l++) {
        if (tid < D) {
            float a = 0.f;
            const float* pr = posw + l * D;
            for (int d = 0; d < D; d++) a = fmaf(pr[d], w1[d * D + tid], a);
            const float* hr = h + l * D;
            for (int d = 0; d < D; d++) a = fmaf(hr[d], w1[(D + d) * D + tid], a);
            nh1[tid] = tanhf(a);
        }
        __syncthreads();
        float val = 0.f;
        if (tid < D) {
            float a = glu1b[tid] + g2[tid];
            for (int d = 0; d < D; d++) a = fmaf(nh1[d], glu1w[d * D + tid], a);
            float sg = 1.f / (1.f + expf(-a));
            val = sg * w2[tid];
        }
        red[tid] = val;
        __syncthreads();
        if (tid < 64) red[tid] += red[tid + 256];
        __syncthreads();
        for (int st = 128; st > 0; st >>= 1) {
            if (tid < st) red[tid] += red[tid + st];
            __syncthreads();
        }
        if (tid == 0) beta[l] = red[0] * mm[l];
        __syncthreads();
    }
    float s2 = 0.f;
    if (tid < D) {
        float a = 0.f;
        for (int l = 0; l < LL; l++) a = fmaf(beta[l], h[l * D + tid], a);
        sessv[tid] = a;
        s2 = a * a;
    }
    red[tid] = s2;
    __syncthreads();
    if (tid < 64) red[tid] += red[tid + 256];
    __syncthreads();
    for (int st = 128; st > 0; st >>= 1) {
        if (tid < st) red[tid] += red[tid + st];
        __syncthreads();
    }
    float scale = 10.f / fmaxf(sqrtf(red[0]), 1e-12f);
    __syncthreads();
    if (tid < D) sessv[tid] = sessv[tid] * scale;
    __syncthreads();
    if (tid < D) {
        g_sess[b * D + tid] = sessv[tid];
        float a = 0.f;
        for (int d = 0; d < D; d++) a = fmaf(sessv[d], mapd[d * D + tid], a);
        out[O_SESSMAP + (size_t)b * D + tid] = a;
    }
}

// ------------------------------------------------------------ scores
__global__ void __launch_bounds__(256) k_scores(float* __restrict__ out) {
    __shared__ float ss[32 * D];
    int half = blockIdx.y;
    for (int i = threadIdx.x; i < 32 * D; i += 256) ss[i] = g_sess[half * 32 * D + i];
    __syncthreads();
    int n = blockIdx.x * 256 + threadIdx.x;
    if (n >= NIT) return;
    float acc[32];
    #pragma unroll
    for (int b = 0; b < 32; b++) acc[b] = 0.f;
    const float* gi = g_items + (size_t)n * DP;
    for (int d = 0; d < D; d += 4) {
        float4 v = *(const float4*)(gi + d);
        #pragma unroll
        for (int b = 0; b < 32; b++) {
            float4 s4 = *(const float4*)(ss + b * D + d);
            acc[b] = fmaf(v.x, s4.x, acc[b]);
            acc[b] = fmaf(v.y, s4.y, acc[b]);
            acc[b] = fmaf(v.z, s4.z, acc[b]);
            acc[b] = fmaf(v.w, s4.w, acc[b]);
        }
    }
    float inv = g_invnorm[n];
    #pragma unroll
    for (int b = 0; b < 32; b++)
        out[O_SCORES + (size_t)(half * 32 + b) * NIT + n] = acc[b] * inv;
}

// ------------------------------------------------------------ loss
__global__ void __launch_bounds__(256) k_loss1(const float* __restrict__ out,
                                               const int* __restrict__ targets) {
    __shared__ float red[256];
    int b = blockIdx.x, tid = threadIdx.x;
    const float* row = out + O_SCORES + (size_t)b * NIT;
    float mx = -3.4e38f;
    for (int n = tid; n < NIT; n += 256) mx = fmaxf(mx, row[n]);
    red[tid] = mx; __syncthreads();
    for (int s = 128; s; s >>= 1) { if (tid < s) red[tid] = fmaxf(red[tid], red[tid + s]); __syncthreads(); }
    float m = red[0]; __syncthreads();
    float se = 0.f;
    for (int n = tid; n < NIT; n += 256) se += expf(row[n] - m);
    red[tid] = se; __syncthreads();
    for (int s = 128; s; s >>= 1) { if (tid < s) red[tid] += red[tid + s]; __syncthreads(); }
    if (tid == 0) {
        int lbl = targets[b] - 1;
        g_red[b] = m + logf(red[0]) - row[lbl];
    }
}

__global__ void k_loss2(float* __restrict__ out) {
    __shared__ float red[64];
    int tid = threadIdx.x;
    red[tid] = g_red[tid];
    __syncthreads();
    for (int s = 32; s; s >>= 1) { if (tid < s) red[tid] += red[tid + s]; __syncthreads(); }
    if (tid == 0) out[0] = red[0] / 64.f;
}

// ------------------------------------------------------------ softmax normalizer
// Z bits proven irrelevant to ranking (R5 == R8) — compute fast, parallel,
// using the same XLA exp poly.
__global__ void __launch_bounds__(1024) k_znorm() {
    __shared__ float sred[32];
    int r = blockIdx.x;
    int t = threadIdx.x;
    int lane = t & 31, warp = t >> 5;
    const float* row = g_sim + (size_t)r * SIMLD;
    float mx = -3.4e38f;
    for (int i = t; i < NIT; i += 1024) mx = fmaxf(mx, row[i]);
    #pragma unroll
    for (int o = 16; o; o >>= 1) mx = fmaxf(mx, __shfl_down_sync(0xffffffffu, mx, o));
    if (lane == 0) sred[warp] = mx;
    __syncthreads();
    if (warp == 0) {
        float v = sred[lane];
        #pragma unroll
        for (int o = 16; o; o >>= 1) v = fmaxf(v, __shfl_down_sync(0xffffffffu, v, o));
        if (lane == 0) sred[0] = v;
    }
    __syncthreads();
    float m = sred[0];
    float acc = 0.f;
    for (int i = t; i < NIT; i += 1024) acc += exp_xla(row[i] - m);
    #pragma unroll
    for (int o = 16; o; o >>= 1) acc += __shfl_down_sync(0xffffffffu, acc, o);
    if (lane == 0) sred[warp] = acc;
    __syncthreads();
    if (warp == 0) {
        float v = sred[lane];
        #pragma unroll
        for (int o = 16; o; o >>= 1) v += __shfl_down_sync(0xffffffffu, v, o);
        if (lane == 0) { g_Z[r] = v; g_M[r] = m; }
    }
}

// ------------------------------------------------------------ topk (softmax-quantized ranking) + gather
__global__ void __launch_bounds__(256) k_topk(const int* __restrict__ slices,
                                              float* __restrict__ out) {
    __shared__ unsigned hist[4096];
    __shared__ float cval[2048];
    __shared__ int cidx[2048];
    __shared__ int sel[100];
    __shared__ int slc[LL];
    __shared__ int s_T, s_n;
    __shared__ float rv[256];
    __shared__ int rp[256];
    int r = blockIdx.x, tid = threadIdx.x;
    const float* row = g_sim + (size_t)r * SIMLD;
    for (int i = tid; i < 4096; i += 256) hist[i] = 0;
    if (tid < LL) slc[tid] = slices[tid];
    if (tid == 0) s_n = 0;
    __syncthreads();
    // pass A: logit histogram (monotone proxy for p-order)
    for (int n = tid; n < NIT; n += 256) {
        unsigned u = __float_as_uint(row[n]);
        u = (u & 0x80000000u) ? ~u : (u | 0x80000000u);
        atomicAdd(&hist[u >> 20], 1u);
    }
    __syncthreads();
    if (tid == 0) {
        int cum = 0, T = 0;
        for (int bb = 4095; bb >= 0; bb--) { cum += (int)hist[bb]; if (cum >= 160) { T = bb; break; } }
        s_T = T;
    }
    __syncthreads();
    int T = s_T;
    // pass B: candidate collection
    for (int n = tid; n < NIT; n += 256) {
        float v = row[n];
        unsigned u = __float_as_uint(v);
        u = (u & 0x80000000u) ? ~u : (u | 0x80000000u);
        if ((int)(u >> 20) >= T) {
            int p = atomicAdd(&s_n, 1);
            if (p < 2048) { cval[p] = v; cidx[p] = n; }
        }
    }
    __syncthreads();
    int nc = min(s_n, 2048);
    float m = g_M[r];
    float Z = g_Z[r];
    // candidate key = fl( exp_xla(fl(v - m)) / Z ) — reference's fp32 chain
    for (int p = tid; p < nc; p += 256) {
        float e = exp_xla(__fsub_rn(cval[p], m));
        cval[p] = __fdiv_rn(e, Z);
    }
    __syncthreads();
    // exact top-100 by (key desc, index asc)
    for (int k = 0; k < 100; k++) {
        float bv = -3.4e38f; int bp = -1, bi = 0x7fffffff;
        for (int p = tid; p < nc; p += 256) {
            float v = cval[p]; int i = cidx[p];
            if (v > bv || (v == bv && i < bi)) { bv = v; bi = i; bp = p; }
        }
        rv[tid] = bv; rp[tid] = bp;
        __syncthreads();
        for (int s = 128; s; s >>= 1) {
            if (tid < s) {
                float ov = rv[tid + s]; int op = rp[tid + s];
                int oi = (op >= 0) ? cidx[op] : 0x7fffffff;
                int mi = (rp[tid] >= 0) ? cidx[rp[tid]] : 0x7fffffff;
                if (ov > rv[tid] || (ov == rv[tid] && oi < mi)) { rv[tid] = ov; rp[tid] = op; }
            }
            __syncthreads();
        }
        if (tid == 0) {
            int p = rp[0];
            sel[k] = cidx[p];
            cval[p] = -3.4e38f; cidx[p] = 0x7fffffff;
        }
        __syncthreads();
    }
    size_t base = (r < NROWS / 2) ? (size_t)O_SUB : (size_t)O_COMP;
    int rr = (r < NROWS / 2) ? r : r - NROWS / 2;
    int b = rr / 100, l = (rr % 100) / 5, s = rr % 5;
    base += ((size_t)((b * LL + l) * 100 + s * LL)) * D;
    for (int i = tid; i < LL * D; i += 256) {
        int e = i / D, d = i % D;
        int idx = sel[slc[e]];
        out[base + (size_t)e * D + d] = g_mapped[(size_t)idx * D + d];
    }
}

// ------------------------------------------------------------ launch
extern "C" void kernel_launch(void* const* d_in, const int* in_sizes, int n_in,
                              void* d_out, int out_size) {
    const float* emb    = (const float*)d_in[0];
    const float* posw   = (const float*)d_in[1];
    const float* w1     = (const float*)d_in[2];
    const float* w2     = (const float*)d_in[3];
    const float* glu1w  = (const float*)d_in[4];
    const float* glu1b  = (const float*)d_in[5];
    const float* glu2w  = (const float*)d_in[6];
    const float* mapd   = (const float*)d_in[7];
    const int*   inputs = (const int*)d_in[8];
    const int*   targets= (const int*)d_in[9];
    const int*   masks  = (const int*)d_in[10];
    const int*   viewed = (const int*)d_in[11];
    const int*   bought = (const int*)d_in[12];
    const int*   slices = (const int*)d_in[13];
    float* out = (float*)d_out;

    float* items_p; cudaGetSymbolAddress((void**)&items_p, g_items);
    float* samp_p;  cudaGetSymbolAddress((void**)&samp_p,  g_samp);
    float* wt_p;    cudaGetSymbolAddress((void**)&wt_p,    g_wt);
    float* map_p;   cudaGetSymbolAddress((void**)&map_p,   g_mapped);
    float* sim_p;   cudaGetSymbolAddress((void**)&sim_p,   g_sim);

    k_prep_items<<<(NIT + 7) / 8, 256>>>(emb);
    k_samp<<<(NROWS + 7) / 8, 256>>>(emb, viewed, bought);
    k_wt<<<(D * DP + 255) / 256, 256>>>(mapd);

    {   // mapped_all = all_item @ map_dense
        dim3 g((D + 127) / 128, (NIT + 127) / 128);
        sgemm_nt<<<g, 256>>>(items_p, DP, wt_p, DP, map_p, D, NIT, D, DP);
    }
    {   // sim = samp @ items^T
        dim3 g((NIT + 127) / 128, (NROWS + 127) / 128);
        sgemm_nt<<<g, 256>>>(samp_p, DP, items_p, DP, sim_p, SIMLD, NROWS, NIT, DP);
    }

    k_sess<<<BB, 320>>>(emb, posw, w1, w2, glu1w, glu1b, glu2w, mapd, inputs, masks, out);
    {
        dim3 g((NIT + 255) / 256, 2);
        k_scores<<<g, 256>>>(out);
    }
    k_loss1<<<BB, 256>>>(out, targets);
    k_loss2<<<1, 64>>>(out);
    k_znorm<<<NROWS, 1024>>>();
    k_topk<<<NROWS, 256>>>(slices, out);
}

// round 12
// speedup vs baseline: 1.0380x; 1.0380x over previous
#include <cuda_runtime.h>
#include <cstdint>
#include <cmath>

#define NUM_ITEMS 40000
#define NIT 39999
#define D 300
#define DP 304
#define BB 64
#define LL 20
#define SS 5
#define NROWS 12800
#define SIMLD 40000
#define NCHUNK 10
#define CROWS 1280

#define O_SCORES 1L
#define O_SUB    2559937L
#define O_COMP   40959937L
#define O_SESSMAP 79359937L

static __device__ float g_sim[(size_t)NROWS * SIMLD];
static __device__ float g_items[(size_t)NIT * DP];
static __device__ float g_samp[(size_t)NROWS * DP];
static __device__ float g_mapped[(size_t)NIT * D];
static __device__ float g_wt[(size_t)D * DP];
static __device__ float g_invnorm[NIT];
static __device__ float g_sess[BB * D];
static __device__ float g_red[BB];

// ------------------------------------------------------------ XLA-CPU / Cephes exp replica
__device__ __forceinline__ float exp_xla(float x) {
    x = fminf(x, 88.3762626647950f);
    x = fmaxf(x, -88.3762626647949f);
    float fx = floorf(__fmaf_rn(x, 1.44269504088896341f, 0.5f));
    float tmp = __fmul_rn(0.693359375f, fx);
    float z   = __fmul_rn(-2.12194440e-4f, fx);
    float r   = __fsub_rn(x, tmp);
    r = __fsub_rn(r, z);
    float zz = __fmul_rn(r, r);
    float y = __fmaf_rn(r, 1.9875691500E-4f, 1.3981999507E-3f);
    y = __fmaf_rn(y, r, 8.3334519073E-3f);
    y = __fmaf_rn(y, r, 4.1665795894E-2f);
    y = __fmaf_rn(y, r, 1.6666665459E-1f);
    y = __fmaf_rn(y, r, 5.0000001201E-1f);
    y = __fmaf_rn(y, zz, r);
    y = __fadd_rn(y, 1.0f);
    int emm0 = (((int)fx) + 127) << 23;
    return __fmul_rn(y, __int_as_float(emm0));
}

// ------------------------------------------------------------ prep
__global__ void k_prep_items(const float* __restrict__ emb) {
    int w = (blockIdx.x * blockDim.x + threadIdx.x) >> 5;
    int lane = threadIdx.x & 31;
    if (w >= NIT) return;
    const float* src = emb + (size_t)(w + 1) * D;
    float* dst = g_items + (size_t)w * DP;
    float ss = 0.f;
    for (int k = lane; k < DP; k += 32) {
        float v = (k < D) ? src[k] : 0.f;
        dst[k] = v;
        ss += v * v;
    }
    #pragma unroll
    for (int o = 16; o; o >>= 1) ss += __shfl_xor_sync(0xffffffffu, ss, o);
    if (lane == 0) g_invnorm[w] = 1.f / fmaxf(sqrtf(ss), 1e-12f);
}

__global__ void k_samp(const float* __restrict__ emb,
                       const int* __restrict__ viewed,
                       const int* __restrict__ bought) {
    int w = (blockIdx.x * blockDim.x + threadIdx.x) >> 5;
    int lane = threadIdx.x & 31;
    if (w >= NROWS) return;
    int idx = (w < NROWS / 2) ? viewed[w] : bought[w - NROWS / 2];
    const float* src = emb + (size_t)idx * D;
    float* dst = g_samp + (size_t)w * DP;
    for (int k = lane; k < DP; k += 32) dst[k] = (k < D) ? src[k] : 0.f;
}

__global__ void k_wt(const float* __restrict__ W) {
    int g = blockIdx.x * blockDim.x + threadIdx.x;
    if (g >= D * DP) return;
    int j = g / DP, d = g % DP;
    g_wt[g] = (d < D) ? W[d * D + j] : 0.f;
}

// ------------------------------------------------------------ SGEMM C = A * B^T (sequential k, fp32 fma — Eigen gebp order)
__global__ void __launch_bounds__(256, 2) sgemm_nt(
    const float* __restrict__ A, int lda,
    const float* __restrict__ Bm, int ldb,
    float* __restrict__ C, int ldc,
    int M, int N, int K)
{
    __shared__ float As[2][8][128];
    __shared__ float Bs[2][8][128];
    int tid = threadIdx.x;
    int bm = blockIdx.y << 7, bn = blockIdx.x << 7;
    int lrow = tid >> 1;
    int lk = (tid & 1) << 2;
    const float* Ap = A + (size_t)(bm + lrow) * lda + lk;
    const float* Bp = Bm + (size_t)(bn + lrow) * ldb + lk;
    bool avld = (bm + lrow) < M;
    bool bvld = (bn + lrow) < N;
    float4 za = make_float4(0.f, 0.f, 0.f, 0.f);
    float4 ra = avld ? *(const float4*)Ap : za;
    float4 rb = bvld ? *(const float4*)Bp : za;
    As[0][lk + 0][lrow] = ra.x; As[0][lk + 1][lrow] = ra.y;
    As[0][lk + 2][lrow] = ra.z; As[0][lk + 3][lrow] = ra.w;
    Bs[0][lk + 0][lrow] = rb.x; Bs[0][lk + 1][lrow] = rb.y;
    Bs[0][lk + 2][lrow] = rb.z; Bs[0][lk + 3][lrow] = rb.w;
    __syncthreads();
    float acc[8][8];
    #pragma unroll
    for (int i = 0; i < 8; i++)
        #pragma unroll
        for (int j = 0; j < 8; j++) acc[i][j] = 0.f;
    int ty = tid >> 4, tx = tid & 15;
    int buf = 0;
    for (int k0 = 8; k0 <= K; k0 += 8) {
        float4 na = za, nb = za;
        if (k0 < K) {
            na = avld ? *(const float4*)(Ap + k0) : za;
            nb = bvld ? *(const float4*)(Bp + k0) : za;
        }
        #pragma unroll
        for (int kk = 0; kk < 8; kk++) {
            float af[8], bf[8];
            *(float4*)(af)     = *(const float4*)(&As[buf][kk][ty << 3]);
            *(float4*)(af + 4) = *(const float4*)(&As[buf][kk][(ty << 3) + 4]);
            *(float4*)(bf)     = *(const float4*)(&Bs[buf][kk][tx << 3]);
            *(float4*)(bf + 4) = *(const float4*)(&Bs[buf][kk][(tx << 3) + 4]);
            #pragma unroll
            for (int i = 0; i < 8; i++)
                #pragma unroll
                for (int j = 0; j < 8; j++)
                    acc[i][j] = fmaf(af[i], bf[j], acc[i][j]);
        }
        if (k0 < K) {
            buf ^= 1;
            As[buf][lk + 0][lrow] = na.x; As[buf][lk + 1][lrow] = na.y;
            As[buf][lk + 2][lrow] = na.z; As[buf][lk + 3][lrow] = na.w;
            Bs[buf][lk + 0][lrow] = nb.x; Bs[buf][lk + 1][lrow] = nb.y;
            Bs[buf][lk + 2][lrow] = nb.z; Bs[buf][lk + 3][lrow] = nb.w;
            __syncthreads();
        }
    }
    #pragma unroll
    for (int i = 0; i < 8; i++) {
        int m = bm + (ty << 3) + i;
        if (m >= M) continue;
        float* crow = C + (size_t)m * ldc + bn + (tx << 3);
        int ncol = bn + (tx << 3);
        #pragma unroll
        for (int j = 0; j < 8; j++)
            if (ncol + j < N) crow[j] = acc[i][j];
    }
}

// ------------------------------------------------------------ session MLP
__global__ void __launch_bounds__(320) k_sess(
    const float* __restrict__ emb, const float* __restrict__ posw,
    const float* __restrict__ w1, const float* __restrict__ w2,
    const float* __restrict__ glu1w, const float* __restrict__ glu1b,
    const float* __restrict__ glu2w, const float* __restrict__ mapd,
    const int* __restrict__ inputs, const int* __restrict__ masks,
    float* __restrict__ out)
{
    __shared__ float h[LL * D];
    __shared__ float nh1[D];
    __shared__ float hs[D];
    __shared__ float g2[D];
    __shared__ float sessv[D];
    __shared__ float red[320];
    __shared__ float beta[LL];
    __shared__ float mm[LL];
    int b = blockIdx.x, tid = threadIdx.x;
    if (tid < LL) mm[tid] = (float)masks[b * LL + tid];
    __syncthreads();
    if (tid < D) {
        float cnt = 0.f;
        for (int l = 0; l < LL; l++) {
            int idx = inputs[b * LL + l];
            h[l * D + tid] = (idx == 0) ? 0.f : emb[(size_t)idx * D + tid];
            cnt += mm[l];
        }
        float acc = 0.f;
        for (int l = 0; l < LL; l++) acc = fmaf(mm[l], h[l * D + tid], acc);
        hs[tid] = acc / cnt;
    }
    __syncthreads();
    if (tid < D) {
        float g = 0.f;
        for (int d = 0; d < D; d++) g = fmaf(hs[d], glu2w[d * D + tid], g);
        g2[tid] = g;
    }
    __syncthreads();
    for (int l = 0; l < LL; l++) {
        if (tid < D) {
            float a = 0.f;
            const float* pr = posw + l * D;
            for (int d = 0; d < D; d++) a = fmaf(pr[d], w1[d * D + tid], a);
            const float* hr = h + l * D;
            for (int d = 0; d < D; d++) a = fmaf(hr[d], w1[(D + d) * D + tid], a);
            nh1[tid] = tanhf(a);
        }
        __syncthreads();
        float val = 0.f;
        if (tid < D) {
            float a = glu1b[tid] + g2[tid];
            for (int d = 0; d < D; d++) a = fmaf(nh1[d], glu1w[d * D + tid], a);
            float sg = 1.f / (1.f + expf(-a));
            val = sg * w2[tid];
        }
        red[tid] = val;
        __syncthreads();
        if (tid < 64) red[tid] += red[tid + 256];
        __syncthreads();
        for (int st = 128; st > 0; st >>= 1) {
            if (tid < st) red[tid] += red[tid + st];
            __syncthreads();
        }
        if (tid == 0) beta[l] = red[0] * mm[l];
        __syncthreads();
    }
    float s2 = 0.f;
    if (tid < D) {
        float a = 0.f;
        for (int l = 0; l < LL; l++) a = fmaf(beta[l], h[l * D + tid], a);
        sessv[tid] = a;
        s2 = a * a;
    }
    red[tid] = s2;
    __syncthreads();
    if (tid < 64) red[tid] += red[tid + 256];
    __syncthreads();
    for (int st = 128; st > 0; st >>= 1) {
        if (tid < st) red[tid] += red[tid + st];
        __syncthreads();
    }
    float scale = 10.f / fmaxf(sqrtf(red[0]), 1e-12f);
    __syncthreads();
    if (tid < D) sessv[tid] = sessv[tid] * scale;
    __syncthreads();
    if (tid < D) {
        g_sess[b * D + tid] = sessv[tid];
        float a = 0.f;
        for (int d = 0; d < D; d++) a = fmaf(sessv[d], mapd[d * D + tid], a);
        out[O_SESSMAP + (size_t)b * D + tid] = a;
    }
}

// ------------------------------------------------------------ scores
__global__ void __launch_bounds__(256) k_scores(float* __restrict__ out) {
    __shared__ float ss[32 * D];
    int half = blockIdx.y;
    for (int i = threadIdx.x; i < 32 * D; i += 256) ss[i] = g_sess[half * 32 * D + i];
    __syncthreads();
    int n = blockIdx.x * 256 + threadIdx.x;
    if (n >= NIT) return;
    float acc[32];
    #pragma unroll
    for (int b = 0; b < 32; b++) acc[b] = 0.f;
    const float* gi = g_items + (size_t)n * DP;
    for (int d = 0; d < D; d += 4) {
        float4 v = *(const float4*)(gi + d);
        #pragma unroll
        for (int b = 0; b < 32; b++) {
            float4 s4 = *(const float4*)(ss + b * D + d);
            acc[b] = fmaf(v.x, s4.x, acc[b]);
            acc[b] = fmaf(v.y, s4.y, acc[b]);
            acc[b] = fmaf(v.z, s4.z, acc[b]);
            acc[b] = fmaf(v.w, s4.w, acc[b]);
        }
    }
    float inv = g_invnorm[n];
    #pragma unroll
    for (int b = 0; b < 32; b++)
        out[O_SCORES + (size_t)(half * 32 + b) * NIT + n] = acc[b] * inv;
}

// ------------------------------------------------------------ loss
__global__ void __launch_bounds__(256) k_loss1(const float* __restrict__ out,
                                               const int* __restrict__ targets) {
    __shared__ float red[256];
    int b = blockIdx.x, tid = threadIdx.x;
    const float* row = out + O_SCORES + (size_t)b * NIT;
    float mx = -3.4e38f;
    for (int n = tid; n < NIT; n += 256) mx = fmaxf(mx, row[n]);
    red[tid] = mx; __syncthreads();
    for (int s = 128; s; s >>= 1) { if (tid < s) red[tid] = fmaxf(red[tid], red[tid + s]); __syncthreads(); }
    float m = red[0]; __syncthreads();
    float se = 0.f;
    for (int n = tid; n < NIT; n += 256) se += expf(row[n] - m);
    red[tid] = se; __syncthreads();
    for (int s = 128; s; s >>= 1) { if (tid < s) red[tid] += red[tid + s]; __syncthreads(); }
    if (tid == 0) {
        int lbl = targets[b] - 1;
        g_red[b] = m + logf(red[0]) - row[lbl];
    }
}

__global__ void k_loss2(float* __restrict__ out) {
    __shared__ float red[64];
    int tid = threadIdx.x;
    red[tid] = g_red[tid];
    __syncthreads();
    for (int s = 32; s; s >>= 1) { if (tid < s) red[tid] += red[tid + s]; __syncthreads(); }
    if (tid == 0) out[0] = red[0] / 64.f;
}

// ------------------------------------------------------------ fused max+hist+Z+topk+gather (one block per row)
__global__ void __launch_bounds__(256) k_topk(const int* __restrict__ slices,
                                              float* __restrict__ out,
                                              int rowoff) {
    __shared__ unsigned hist[4096];
    __shared__ float cval[2048];
    __shared__ int cidx[2048];
    __shared__ int sel[100];
    __shared__ int slc[LL];
    __shared__ int s_T, s_n;
    __shared__ float rv[256];
    __shared__ int rp[256];
    __shared__ float s_m, s_Z;
    int r = rowoff + blockIdx.x, tid = threadIdx.x;
    const float* row = g_sim + (size_t)r * SIMLD;
    for (int i = tid; i < 4096; i += 256) hist[i] = 0;
    if (tid < LL) slc[tid] = slices[tid];
    if (tid == 0) s_n = 0;
    __syncthreads();
    // pass A: row max + logit histogram
    float mx = -3.4e38f;
    for (int n = tid; n < NIT; n += 256) {
        float v = row[n];
        mx = fmaxf(mx, v);
        unsigned u = __float_as_uint(v);
        u = (u & 0x80000000u) ? ~u : (u | 0x80000000u);
        atomicAdd(&hist[u >> 20], 1u);
    }
    rv[tid] = mx;
    __syncthreads();
    for (int s = 128; s; s >>= 1) { if (tid < s) rv[tid] = fmaxf(rv[tid], rv[tid + s]); __syncthreads(); }
    if (tid == 0) {
        s_m = rv[0];
        int cum = 0, T = 0;
        for (int bb = 4095; bb >= 0; bb--) { cum += (int)hist[bb]; if (cum >= 160) { T = bb; break; } }
        s_T = T;
    }
    __syncthreads();
    int T = s_T;
    float m = s_m;
    // pass B: Z (exp_xla; Z bits proven ranking-invariant) + candidate collection
    float zacc = 0.f;
    for (int n = tid; n < NIT; n += 256) {
        float v = row[n];
        zacc += exp_xla(v - m);
        unsigned u = __float_as_uint(v);
        u = (u & 0x80000000u) ? ~u : (u | 0x80000000u);
        if ((int)(u >> 20) >= T) {
            int p = atomicAdd(&s_n, 1);
            if (p < 2048) { cval[p] = v; cidx[p] = n; }
        }
    }
    rv[tid] = zacc;
    __syncthreads();
    for (int s = 128; s; s >>= 1) { if (tid < s) rv[tid] += rv[tid + s]; __syncthreads(); }
    if (tid == 0) s_Z = rv[0];
    __syncthreads();
    int nc = min(s_n, 2048);
    float Z = s_Z;
    // candidate key = fl( exp_xla(fl(v - m)) / Z ) — reference's fp32 chain
    for (int p = tid; p < nc; p += 256) {
        float e = exp_xla(__fsub_rn(cval[p], m));
        cval[p] = __fdiv_rn(e, Z);
    }
    __syncthreads();
    // exact top-100 by (key desc, index asc)
    for (int k = 0; k < 100; k++) {
        float bv = -3.4e38f; int bp = -1, bi = 0x7fffffff;
        for (int p = tid; p < nc; p += 256) {
            float v = cval[p]; int i = cidx[p];
            if (v > bv || (v == bv && i < bi)) { bv = v; bi = i; bp = p; }
        }
        rv[tid] = bv; rp[tid] = bp;
        __syncthreads();
        for (int s = 128; s; s >>= 1) {
            if (tid < s) {
                float ov = rv[tid + s]; int op = rp[tid + s];
                int oi = (op >= 0) ? cidx[op] : 0x7fffffff;
                int mi = (rp[tid] >= 0) ? cidx[rp[tid]] : 0x7fffffff;
                if (ov > rv[tid] || (ov == rv[tid] && oi < mi)) { rv[tid] = ov; rp[tid] = op; }
            }
            __syncthreads();
        }
        if (tid == 0) {
            int p = rp[0];
            sel[k] = cidx[p];
            cval[p] = -3.4e38f; cidx[p] = 0x7fffffff;
        }
        __syncthreads();
    }
    size_t base = (r < NROWS / 2) ? (size_t)O_SUB : (size_t)O_COMP;
    int rr = (r < NROWS / 2) ? r : r - NROWS / 2;
    int b = rr / 100, l = (rr % 100) / 5, s = rr % 5;
    base += ((size_t)((b * LL + l) * 100 + s * LL)) * D;
    for (int i = tid; i < LL * D; i += 256) {
        int e = i / D, d = i % D;
        int idx = sel[slc[e]];
        out[base + (size_t)e * D + d] = g_mapped[(size_t)idx * D + d];
    }
}

// ------------------------------------------------------------ launch (fork-join dual-stream capture)
extern "C" void kernel_launch(void* const* d_in, const int* in_sizes, int n_in,
                              void* d_out, int out_size) {
    const float* emb    = (const float*)d_in[0];
    const float* posw   = (const float*)d_in[1];
    const float* w1     = (const float*)d_in[2];
    const float* w2     = (const float*)d_in[3];
    const float* glu1w  = (const float*)d_in[4];
    const float* glu1b  = (const float*)d_in[5];
    const float* glu2w  = (const float*)d_in[6];
    const float* mapd   = (const float*)d_in[7];
    const int*   inputs = (const int*)d_in[8];
    const int*   targets= (const int*)d_in[9];
    const int*   masks  = (const int*)d_in[10];
    const int*   viewed = (const int*)d_in[11];
    const int*   bought = (const int*)d_in[12];
    const int*   slices = (const int*)d_in[13];
    float* out = (float*)d_out;

    float* items_p; cudaGetSymbolAddress((void**)&items_p, g_items);
    float* samp_p;  cudaGetSymbolAddress((void**)&samp_p,  g_samp);
    float* wt_p;    cudaGetSymbolAddress((void**)&wt_p,    g_wt);
    float* map_p;   cudaGetSymbolAddress((void**)&map_p,   g_mapped);
    float* sim_p;   cudaGetSymbolAddress((void**)&sim_p,   g_sim);

    static cudaStream_t s1 = nullptr;
    static cudaEvent_t evStart, evPrep, evJoin, evChunk[NCHUNK];
    if (!s1) {
        cudaStreamCreateWithFlags(&s1, cudaStreamNonBlocking);
        cudaEventCreateWithFlags(&evStart, cudaEventDisableTiming);
        cudaEventCreateWithFlags(&evPrep,  cudaEventDisableTiming);
        cudaEventCreateWithFlags(&evJoin,  cudaEventDisableTiming);
        for (int i = 0; i < NCHUNK; i++)
            cudaEventCreateWithFlags(&evChunk[i], cudaEventDisableTiming);
    }

    // fork: s1 joins the capture via evStart
    cudaEventRecord(evStart, 0);
    cudaStreamWaitEvent(s1, evStart, 0);

    // stream 0: prep inputs for the big GEMM
    k_prep_items<<<(NIT + 7) / 8, 256>>>(emb);
    k_samp<<<(NROWS + 7) / 8, 256>>>(emb, viewed, bought);
    cudaEventRecord(evPrep, 0);

    // stream 1: everything independent of the sim GEMM
    k_wt<<<(D * DP + 255) / 256, 256, 0, s1>>>(mapd);
    k_sess<<<BB, 320, 0, s1>>>(emb, posw, w1, w2, glu1w, glu1b, glu2w, mapd, inputs, masks, out);
    cudaStreamWaitEvent(s1, evPrep, 0);
    {   // mapped_all = all_item @ map_dense
        dim3 g((D + 127) / 128, (NIT + 127) / 128);
        sgemm_nt<<<g, 256, 0, s1>>>(items_p, DP, wt_p, DP, map_p, D, NIT, D, DP);
    }
    {
        dim3 g((NIT + 255) / 256, 2);
        k_scores<<<g, 256, 0, s1>>>(out);
    }
    k_loss1<<<BB, 256, 0, s1>>>(out, targets);
    k_loss2<<<1, 64, 0, s1>>>(out);

    // stream 0: sim GEMM in row chunks (bit-identical arithmetic; partitioned grid)
    for (int c = 0; c < NCHUNK; c++) {
        dim3 g((NIT + 127) / 128, CROWS / 128);
        sgemm_nt<<<g, 256>>>(samp_p + (size_t)c * CROWS * DP, DP,
                             items_p, DP,
                             sim_p + (size_t)c * CROWS * SIMLD, SIMLD,
                             CROWS, NIT, DP);
        cudaEventRecord(evChunk[c], 0);
    }

    // stream 1: fused znorm+topk+gather per chunk, overlapped with later GEMM chunks
    for (int c = 0; c < NCHUNK; c++) {
        cudaStreamWaitEvent(s1, evChunk[c], 0);
        k_topk<<<CROWS, 256, 0, s1>>>(slices, out, c * CROWS);
    }

    // join back into the capture stream
    cudaEventRecord(evJoin, s1);
    cudaStreamWaitEvent(0, evJoin, 0);
}

// round 14
// speedup vs baseline: 1.1831x; 1.1398x over previous
#include <cuda_runtime.h>
#include <cstdint>
#include <cmath>

#define NUM_ITEMS 40000
#define NIT 39999
#define D 300
#define DP 304
#define BB 64
#define LL 20
#define SS 5
#define NROWS 12800
#define SIMLD 40000
#define NCHUNK 10
#define CROWS 1280
#define TKT 512

#define O_SCORES 1L
#define O_SUB    2559937L
#define O_COMP   40959937L
#define O_SESSMAP 79359937L

static __device__ float g_sim[(size_t)NROWS * SIMLD];
static __device__ float g_items[(size_t)NIT * DP];
static __device__ float g_samp[(size_t)NROWS * DP];
static __device__ float g_mapped[(size_t)NIT * D];
static __device__ float g_wt[(size_t)D * DP];
static __device__ float g_invnorm[NIT];
static __device__ float g_sess[BB * D];
static __device__ float g_red[BB];

// ------------------------------------------------------------ XLA-CPU / Cephes exp replica
__device__ __forceinline__ float exp_xla(float x) {
    x = fminf(x, 88.3762626647950f);
    x = fmaxf(x, -88.3762626647949f);
    float fx = floorf(__fmaf_rn(x, 1.44269504088896341f, 0.5f));
    float tmp = __fmul_rn(0.693359375f, fx);
    float z   = __fmul_rn(-2.12194440e-4f, fx);
    float r   = __fsub_rn(x, tmp);
    r = __fsub_rn(r, z);
    float zz = __fmul_rn(r, r);
    float y = __fmaf_rn(r, 1.9875691500E-4f, 1.3981999507E-3f);
    y = __fmaf_rn(y, r, 8.3334519073E-3f);
    y = __fmaf_rn(y, r, 4.1665795894E-2f);
    y = __fmaf_rn(y, r, 1.6666665459E-1f);
    y = __fmaf_rn(y, r, 5.0000001201E-1f);
    y = __fmaf_rn(y, zz, r);
    y = __fadd_rn(y, 1.0f);
    int emm0 = (((int)fx) + 127) << 23;
    return __fmul_rn(y, __int_as_float(emm0));
}

// ------------------------------------------------------------ prep
__global__ void k_prep_items(const float* __restrict__ emb) {
    int w = (blockIdx.x * blockDim.x + threadIdx.x) >> 5;
    int lane = threadIdx.x & 31;
    if (w >= NIT) return;
    const float* src = emb + (size_t)(w + 1) * D;
    float* dst = g_items + (size_t)w * DP;
    float ss = 0.f;
    for (int k = lane; k < DP; k += 32) {
        float v = (k < D) ? src[k] : 0.f;
        dst[k] = v;
        ss += v * v;
    }
    #pragma unroll
    for (int o = 16; o; o >>= 1) ss += __shfl_xor_sync(0xffffffffu, ss, o);
    if (lane == 0) g_invnorm[w] = 1.f / fmaxf(sqrtf(ss), 1e-12f);
}

__global__ void k_samp(const float* __restrict__ emb,
                       const int* __restrict__ viewed,
                       const int* __restrict__ bought) {
    int w = (blockIdx.x * blockDim.x + threadIdx.x) >> 5;
    int lane = threadIdx.x & 31;
    if (w >= NROWS) return;
    int idx = (w < NROWS / 2) ? viewed[w] : bought[w - NROWS / 2];
    const float* src = emb + (size_t)idx * D;
    float* dst = g_samp + (size_t)w * DP;
    for (int k = lane; k < DP; k += 32) dst[k] = (k < D) ? src[k] : 0.f;
}

__global__ void k_wt(const float* __restrict__ W) {
    int g = blockIdx.x * blockDim.x + threadIdx.x;
    if (g >= D * DP) return;
    int j = g / DP, d = g % DP;
    g_wt[g] = (d < D) ? W[d * D + j] : 0.f;
}

// ------------------------------------------------------------ SGEMM C = A * B^T (sequential k, fp32 fma — Eigen gebp order)
__global__ void __launch_bounds__(256, 2) sgemm_nt(
    const float* __restrict__ A, int lda,
    const float* __restrict__ Bm, int ldb,
    float* __restrict__ C, int ldc,
    int M, int N, int K)
{
    __shared__ float As[2][8][128];
    __shared__ float Bs[2][8][128];
    int tid = threadIdx.x;
    int bm = blockIdx.y << 7, bn = blockIdx.x << 7;
    int lrow = tid >> 1;
    int lk = (tid & 1) << 2;
    const float* Ap = A + (size_t)(bm + lrow) * lda + lk;
    const float* Bp = Bm + (size_t)(bn + lrow) * ldb + lk;
    bool avld = (bm + lrow) < M;
    bool bvld = (bn + lrow) < N;
    float4 za = make_float4(0.f, 0.f, 0.f, 0.f);
    float4 ra = avld ? *(const float4*)Ap : za;
    float4 rb = bvld ? *(const float4*)Bp : za;
    As[0][lk + 0][lrow] = ra.x; As[0][lk + 1][lrow] = ra.y;
    As[0][lk + 2][lrow] = ra.z; As[0][lk + 3][lrow] = ra.w;
    Bs[0][lk + 0][lrow] = rb.x; Bs[0][lk + 1][lrow] = rb.y;
    Bs[0][lk + 2][lrow] = rb.z; Bs[0][lk + 3][lrow] = rb.w;
    __syncthreads();
    float acc[8][8];
    #pragma unroll
    for (int i = 0; i < 8; i++)
        #pragma unroll
        for (int j = 0; j < 8; j++) acc[i][j] = 0.f;
    int ty = tid >> 4, tx = tid & 15;
    int buf = 0;
    for (int k0 = 8; k0 <= K; k0 += 8) {
        float4 na = za, nb = za;
        if (k0 < K) {
            na = avld ? *(const float4*)(Ap + k0) : za;
            nb = bvld ? *(const float4*)(Bp + k0) : za;
        }
        #pragma unroll
        for (int kk = 0; kk < 8; kk++) {
            float af[8], bf[8];
            *(float4*)(af)     = *(const float4*)(&As[buf][kk][ty << 3]);
            *(float4*)(af + 4) = *(const float4*)(&As[buf][kk][(ty << 3) + 4]);
            *(float4*)(bf)     = *(const float4*)(&Bs[buf][kk][tx << 3]);
            *(float4*)(bf + 4) = *(const float4*)(&Bs[buf][kk][(tx << 3) + 4]);
            #pragma unroll
            for (int i = 0; i < 8; i++)
                #pragma unroll
                for (int j = 0; j < 8; j++)
                    acc[i][j] = fmaf(af[i], bf[j], acc[i][j]);
        }
        if (k0 < K) {
            buf ^= 1;
            As[buf][lk + 0][lrow] = na.x; As[buf][lk + 1][lrow] = na.y;
            As[buf][lk + 2][lrow] = na.z; As[buf][lk + 3][lrow] = na.w;
            Bs[buf][lk + 0][lrow] = nb.x; Bs[buf][lk + 1][lrow] = nb.y;
            Bs[buf][lk + 2][lrow] = nb.z; Bs[buf][lk + 3][lrow] = nb.w;
            __syncthreads();
        }
    }
    #pragma unroll
    for (int i = 0; i < 8; i++) {
        int m = bm + (ty << 3) + i;
        if (m >= M) continue;
        float* crow = C + (size_t)m * ldc + bn + (tx << 3);
        int ncol = bn + (tx << 3);
        #pragma unroll
        for (int j = 0; j < 8; j++)
            if (ncol + j < N) crow[j] = acc[i][j];
    }
}

// ------------------------------------------------------------ session MLP
__global__ void __launch_bounds__(320) k_sess(
    const float* __restrict__ emb, const float* __restrict__ posw,
    const float* __restrict__ w1, const float* __restrict__ w2,
    const float* __restrict__ glu1w, const float* __restrict__ glu1b,
    const float* __restrict__ glu2w, const float* __restrict__ mapd,
    const int* __restrict__ inputs, const int* __restrict__ masks,
    float* __restrict__ out)
{
    __shared__ float h[LL * D];
    __shared__ float nh1[D];
    __shared__ float hs[D];
    __shared__ float g2[D];
    __shared__ float sessv[D];
    __shared__ float red[320];
    __shared__ float beta[LL];
    __shared__ float mm[LL];
    int b = blockIdx.x, tid = threadIdx.x;
    if (tid < LL) mm[tid] = (float)masks[b * LL + tid];
    __syncthreads();
    if (tid < D) {
        float cnt = 0.f;
        for (int l = 0; l < LL; l++) {
            int idx = inputs[b * LL + l];
            h[l * D + tid] = (idx == 0) ? 0.f : emb[(size_t)idx * D + tid];
            cnt += mm[l];
        }
        float acc = 0.f;
        for (int l = 0; l < LL; l++) acc = fmaf(mm[l], h[l * D + tid], acc);
        hs[tid] = acc / cnt;
    }
    __syncthreads();
    if (tid < D) {
        float g = 0.f;
        for (int d = 0; d < D; d++) g = fmaf(hs[d], glu2w[d * D + tid], g);
        g2[tid] = g;
    }
    __syncthreads();
    for (int l = 0; l < LL; l++) {
        if (tid < D) {
            float a = 0.f;
            const float* pr = posw + l * D;
            for (int d = 0; d < D; d++) a = fmaf(pr[d], w1[d * D + tid], a);
            const float* hr = h + l * D;
            for (int d = 0; d < D; d++) a = fmaf(hr[d], w1[(D + d) * D + tid], a);
            nh1[tid] = tanhf(a);
        }
        __syncthreads();
        float val = 0.f;
        if (tid < D) {
            float a = glu1b[tid] + g2[tid];
            for (int d = 0; d < D; d++) a = fmaf(nh1[d], glu1w[d * D + tid], a);
            float sg = 1.f / (1.f + expf(-a));
            val = sg * w2[tid];
        }
        red[tid] = val;
        __syncthreads();
        if (tid < 64) red[tid] += red[tid + 256];
        __syncthreads();
        for (int st = 128; st > 0; st >>= 1) {
            if (tid < st) red[tid] += red[tid + st];
            __syncthreads();
        }
        if (tid == 0) beta[l] = red[0] * mm[l];
        __syncthreads();
    }
    float s2 = 0.f;
    if (tid < D) {
        float a = 0.f;
        for (int l = 0; l < LL; l++) a = fmaf(beta[l], h[l * D + tid], a);
        sessv[tid] = a;
        s2 = a * a;
    }
    red[tid] = s2;
    __syncthreads();
    if (tid < 64) red[tid] += red[tid + 256];
    __syncthreads();
    for (int st = 128; st > 0; st >>= 1) {
        if (tid < st) red[tid] += red[tid + st];
        __syncthreads();
    }
    float scale = 10.f / fmaxf(sqrtf(red[0]), 1e-12f);
    __syncthreads();
    if (tid < D) sessv[tid] = sessv[tid] * scale;
    __syncthreads();
    if (tid < D) {
        g_sess[b * D + tid] = sessv[tid];
        float a = 0.f;
        for (int d = 0; d < D; d++) a = fmaf(sessv[d], mapd[d * D + tid], a);
        out[O_SESSMAP + (size_t)b * D + tid] = a;
    }
}

// ------------------------------------------------------------ scores
__global__ void __launch_bounds__(256) k_scores(float* __restrict__ out) {
    __shared__ float ss[32 * D];
    int half = blockIdx.y;
    for (int i = threadIdx.x; i < 32 * D; i += 256) ss[i] = g_sess[half * 32 * D + i];
    __syncthreads();
    int n = blockIdx.x * 256 + threadIdx.x;
    if (n >= NIT) return;
    float acc[32];
    #pragma unroll
    for (int b = 0; b < 32; b++) acc[b] = 0.f;
    const float* gi = g_items + (size_t)n * DP;
    for (int d = 0; d < D; d += 4) {
        float4 v = *(const float4*)(gi + d);
        #pragma unroll
        for (int b = 0; b < 32; b++) {
            float4 s4 = *(const float4*)(ss + b * D + d);
            acc[b] = fmaf(v.x, s4.x, acc[b]);
            acc[b] = fmaf(v.y, s4.y, acc[b]);
            acc[b] = fmaf(v.z, s4.z, acc[b]);
            acc[b] = fmaf(v.w, s4.w, acc[b]);
        }
    }
    float inv = g_invnorm[n];
    #pragma unroll
    for (int b = 0; b < 32; b++)
        out[O_SCORES + (size_t)(half * 32 + b) * NIT + n] = acc[b] * inv;
}

// ------------------------------------------------------------ loss
__global__ void __launch_bounds__(256) k_loss1(const float* __restrict__ out,
                                               const int* __restrict__ targets) {
    __shared__ float red[256];
    int b = blockIdx.x, tid = threadIdx.x;
    const float* row = out + O_SCORES + (size_t)b * NIT;
    float mx = -3.4e38f;
    for (int n = tid; n < NIT; n += 256) mx = fmaxf(mx, row[n]);
    red[tid] = mx; __syncthreads();
    for (int s = 128; s; s >>= 1) { if (tid < s) red[tid] = fmaxf(red[tid], red[tid + s]); __syncthreads(); }
    float m = red[0]; __syncthreads();
    float se = 0.f;
    for (int n = tid; n < NIT; n += 256) se += expf(row[n] - m);
    red[tid] = se; __syncthreads();
    for (int s = 128; s; s >>= 1) { if (tid < s) red[tid] += red[tid + s]; __syncthreads(); }
    if (tid == 0) {
        int lbl = targets[b] - 1;
        g_red[b] = m + logf(red[0]) - row[lbl];
    }
}

__global__ void k_loss2(float* __restrict__ out) {
    __shared__ float red[64];
    int tid = threadIdx.x;
    red[tid] = g_red[tid];
    __syncthreads();
    for (int s = 32; s; s >>= 1) { if (tid < s) red[tid] += red[tid + s]; __syncthreads(); }
    if (tid == 0) out[0] = red[0] / 64.f;
}

// ------------------------------------------------------------ fused max+hist+Z+topk(sort)+gather — one block per row
__global__ void __launch_bounds__(TKT) k_topk(const int* __restrict__ slices,
                                              float* __restrict__ out,
                                              int rowoff) {
    __shared__ union {
        unsigned hist[4096];
        unsigned long long skey[2048];
    } u;
    __shared__ float cval[2048];
    __shared__ int cidx[2048];
    __shared__ int sel[100];
    __shared__ int slc[LL];
    __shared__ int s_T, s_n;
    __shared__ float rv[TKT];
    __shared__ float s_m, s_Z;
    int r = rowoff + blockIdx.x, tid = threadIdx.x;
    const float* row = g_sim + (size_t)r * SIMLD;
    const float4* rowv = (const float4*)row;
    for (int i = tid; i < 4096; i += TKT) u.hist[i] = 0;
    if (tid < LL) slc[tid] = slices[tid];
    if (tid == 0) s_n = 0;
    __syncthreads();
    // pass A: row max + logit histogram (9999 float4 + 3 scalar tail; elem 39999 is pad garbage)
    float mx = -3.4e38f;
    for (int i = tid; i < 9999; i += TKT) {
        float4 v4 = rowv[i];
        mx = fmaxf(fmaxf(mx, fmaxf(v4.x, v4.y)), fmaxf(v4.z, v4.w));
        unsigned ux = __float_as_uint(v4.x); ux = (ux & 0x80000000u) ? ~ux : (ux | 0x80000000u);
        unsigned uy = __float_as_uint(v4.y); uy = (uy & 0x80000000u) ? ~uy : (uy | 0x80000000u);
        unsigned uz = __float_as_uint(v4.z); uz = (uz & 0x80000000u) ? ~uz : (uz | 0x80000000u);
        unsigned uw = __float_as_uint(v4.w); uw = (uw & 0x80000000u) ? ~uw : (uw | 0x80000000u);
        atomicAdd(&u.hist[ux >> 20], 1u);
        atomicAdd(&u.hist[uy >> 20], 1u);
        atomicAdd(&u.hist[uz >> 20], 1u);
        atomicAdd(&u.hist[uw >> 20], 1u);
    }
    if (tid < 3) {
        float v = row[39996 + tid];
        mx = fmaxf(mx, v);
        unsigned uu = __float_as_uint(v); uu = (uu & 0x80000000u) ? ~uu : (uu | 0x80000000u);
        atomicAdd(&u.hist[uu >> 20], 1u);
    }
    rv[tid] = mx;
    __syncthreads();
    for (int s = TKT / 2; s; s >>= 1) { if (tid < s) rv[tid] = fmaxf(rv[tid], rv[tid + s]); __syncthreads(); }
    if (tid == 0) {
        s_m = rv[0];
        int cum = 0, T = 0;
        for (int bb = 4095; bb >= 0; bb--) { cum += (int)u.hist[bb]; if (cum >= 160) { T = bb; break; } }
        s_T = T;
    }
    __syncthreads();
    unsigned T = (unsigned)s_T;
    float m = s_m;
    // pass B: Z (exp_xla; Z bits ranking-invariant) + candidate collection
    float zacc = 0.f;
    for (int i = tid; i < 9999; i += TKT) {
        float4 v4 = rowv[i];
        zacc += exp_xla(v4.x - m); zacc += exp_xla(v4.y - m);
        zacc += exp_xla(v4.z - m); zacc += exp_xla(v4.w - m);
        #pragma unroll
        for (int c = 0; c < 4; c++) {
            float v = (c == 0) ? v4.x : (c == 1) ? v4.y : (c == 2) ? v4.z : v4.w;
            unsigned uu = __float_as_uint(v); uu = (uu & 0x80000000u) ? ~uu : (uu | 0x80000000u);
            if ((uu >> 20) >= T) {
                int p = atomicAdd(&s_n, 1);
                if (p < 2048) { cval[p] = v; cidx[p] = 4 * i + c; }
            }
        }
    }
    if (tid < 3) {
        float v = row[39996 + tid];
        zacc += exp_xla(v - m);
        unsigned uu = __float_as_uint(v); uu = (uu & 0x80000000u) ? ~uu : (uu | 0x80000000u);
        if ((uu >> 20) >= T) {
            int p = atomicAdd(&s_n, 1);
            if (p < 2048) { cval[p] = v; cidx[p] = 39996 + tid; }
        }
    }
    rv[tid] = zacc;
    __syncthreads();
    for (int s = TKT / 2; s; s >>= 1) { if (tid < s) rv[tid] += rv[tid + s]; __syncthreads(); }
    if (tid == 0) s_Z = rv[0];
    __syncthreads();
    int nc = min(s_n, 2048);
    float Z = s_Z;
    int n = 128;
    while (n < nc) n <<= 1;
    // build sort keys: (p_bits << 24) | (0xFFFFFF - idx)  — hist is dead, alias as skey
    for (int p = tid; p < n; p += TKT) {
        if (p < nc) {
            float e = exp_xla(__fsub_rn(cval[p], m));
            float pr = __fdiv_rn(e, Z);
            u.skey[p] = ((unsigned long long)__float_as_uint(pr) << 24)
                      | (unsigned)(0xFFFFFF - cidx[p]);
        } else {
            u.skey[p] = 0ull;
        }
    }
    __syncthreads();
    // bitonic sort descending, n elements
    for (int k2 = 2; k2 <= n; k2 <<= 1) {
        for (int j = k2 >> 1; j > 0; j >>= 1) {
            for (int i = tid; i < n; i += TKT) {
                int l = i ^ j;
                if (l > i) {
                    unsigned long long a = u.skey[i], b = u.skey[l];
                    bool up = ((i & k2) == 0);
                    if (up ? (a < b) : (a > b)) { u.skey[i] = b; u.skey[l] = a; }
                }
            }
            __syncthreads();
        }
    }
    if (tid < 100)
        sel[tid] = 0xFFFFFF - (int)(u.skey[tid] & 0xFFFFFFull);
    __syncthreads();
    size_t base = (r < NROWS / 2) ? (size_t)O_SUB : (size_t)O_COMP;
    int rr = (r < NROWS / 2) ? r : r - NROWS / 2;
    int b = rr / 100, l = (rr % 100) / 5, s = rr % 5;
    base += ((size_t)((b * LL + l) * 100 + s * LL)) * D;
    for (int i = tid; i < LL * D; i += TKT) {
        int e = i / D, d = i % D;
        int idx = sel[slc[e]];
        out[base + (size_t)e * D + d] = g_mapped[(size_t)idx * D + d];
    }
}

// ------------------------------------------------------------ launch (fork-join dual-stream capture)
extern "C" void kernel_launch(void* const* d_in, const int* in_sizes, int n_in,
                              void* d_out, int out_size) {
    const float* emb    = (const float*)d_in[0];
    const float* posw   = (const float*)d_in[1];
    const float* w1     = (const float*)d_in[2];
    const float* w2     = (const float*)d_in[3];
    const float* glu1w  = (const float*)d_in[4];
    const float* glu1b  = (const float*)d_in[5];
    const float* glu2w  = (const float*)d_in[6];
    const float* mapd   = (const float*)d_in[7];
    const int*   inputs = (const int*)d_in[8];
    const int*   targets= (const int*)d_in[9];
    const int*   masks  = (const int*)d_in[10];
    const int*   viewed = (const int*)d_in[11];
    const int*   bought = (const int*)d_in[12];
    const int*   slices = (const int*)d_in[13];
    float* out = (float*)d_out;

    float* items_p; cudaGetSymbolAddress((void**)&items_p, g_items);
    float* samp_p;  cudaGetSymbolAddress((void**)&samp_p,  g_samp);
    float* wt_p;    cudaGetSymbolAddress((void**)&wt_p,    g_wt);
    float* map_p;   cudaGetSymbolAddress((void**)&map_p,   g_mapped);
    float* sim_p;   cudaGetSymbolAddress((void**)&sim_p,   g_sim);

    static cudaStream_t s1 = nullptr;
    static cudaEvent_t evStart, evPrep, evJoin, evChunk[NCHUNK];
    if (!s1) {
        cudaStreamCreateWithFlags(&s1, cudaStreamNonBlocking);
        cudaEventCreateWithFlags(&evStart, cudaEventDisableTiming);
        cudaEventCreateWithFlags(&evPrep,  cudaEventDisableTiming);
        cudaEventCreateWithFlags(&evJoin,  cudaEventDisableTiming);
        for (int i = 0; i < NCHUNK; i++)
            cudaEventCreateWithFlags(&evChunk[i], cudaEventDisableTiming);
    }

    // fork: s1 joins the capture via evStart
    cudaEventRecord(evStart, 0);
    cudaStreamWaitEvent(s1, evStart, 0);

    // stream 0: prep inputs for the big GEMM
    k_prep_items<<<(NIT + 7) / 8, 256>>>(emb);
    k_samp<<<(NROWS + 7) / 8, 256>>>(emb, viewed, bought);
    cudaEventRecord(evPrep, 0);

    // stream 1: everything independent of the sim GEMM
    k_wt<<<(D * DP + 255) / 256, 256, 0, s1>>>(mapd);
    k_sess<<<BB, 320, 0, s1>>>(emb, posw, w1, w2, glu1w, glu1b, glu2w, mapd, inputs, masks, out);
    cudaStreamWaitEvent(s1, evPrep, 0);
    {   // mapped_all = all_item @ map_dense
        dim3 g((D + 127) / 128, (NIT + 127) / 128);
        sgemm_nt<<<g, 256, 0, s1>>>(items_p, DP, wt_p, DP, map_p, D, NIT, D, DP);
    }
    {
        dim3 g((NIT + 255) / 256, 2);
        k_scores<<<g, 256, 0, s1>>>(out);
    }
    k_loss1<<<BB, 256, 0, s1>>>(out, targets);
    k_loss2<<<1, 64, 0, s1>>>(out);

    // stream 0: sim GEMM in row chunks (bit-identical arithmetic; partitioned grid)
    for (int c = 0; c < NCHUNK; c++) {
        dim3 g((NIT + 127) / 128, CROWS / 128);
        sgemm_nt<<<g, 256>>>(samp_p + (size_t)c * CROWS * DP, DP,
                             items_p, DP,
                             sim_p + (size_t)c * CROWS * SIMLD, SIMLD,
                             CROWS, NIT, DP);
        cudaEventRecord(evChunk[c], 0);
    }

    // stream 1: fused znorm+topk+gather per chunk, overlapped with later GEMM chunks
    for (int c = 0; c < NCHUNK; c++) {
        cudaStreamWaitEvent(s1, evChunk[c], 0);
        k_topk<<<CROWS, TKT, 0, s1>>>(slices, out, c * CROWS);
    }

    // join back into the capture stream
    cudaEventRecord(evJoin, s1);
    cudaStreamWaitEvent(0, evJoin, 0);
}

// round 15
// speedup vs baseline: 1.1965x; 1.0113x over previous
#include <cuda_runtime.h>
#include <cstdint>
#include <cmath>

#define NUM_ITEMS 40000
#define NIT 39999
#define D 300
#define DP 304
#define BB 64
#define LL 20
#define SS 5
#define NROWS 12800
#define SIMLD 40000
#define NCHUNK 10
#define CROWS 1280
#define TKT 512

#define O_SCORES 1L
#define O_SUB    2559937L
#define O_COMP   40959937L
#define O_SESSMAP 79359937L

static __device__ float g_sim[(size_t)NROWS * SIMLD];
static __device__ float g_items[(size_t)NIT * DP];
static __device__ float g_samp[(size_t)NROWS * DP];
static __device__ float g_mapped[(size_t)NIT * D];
static __device__ float g_wt[(size_t)D * DP];
static __device__ float g_invnorm[NIT];
static __device__ float g_sess[BB * D];
static __device__ float g_red[BB];

// ------------------------------------------------------------ packed f32x2 helpers
__device__ __forceinline__ unsigned long long pack_dup(float a) {
    unsigned long long r;
    unsigned u = __float_as_uint(a);
    asm("mov.b64 %0, {%1, %2};" : "=l"(r) : "r"(u), "r"(u));
    return r;
}
__device__ __forceinline__ unsigned long long fma2(unsigned long long a,
                                                   unsigned long long b,
                                                   unsigned long long c) {
    unsigned long long d;
    asm("fma.rn.f32x2 %0, %1, %2, %3;" : "=l"(d) : "l"(a), "l"(b), "l"(c));
    return d;
}
__device__ __forceinline__ void unpack2(unsigned long long v, float& lo, float& hi) {
    unsigned a, b;
    asm("mov.b64 {%0, %1}, %2;" : "=r"(a), "=r"(b) : "l"(v));
    lo = __uint_as_float(a);
    hi = __uint_as_float(b);
}

// ------------------------------------------------------------ XLA-CPU / Cephes exp replica
__device__ __forceinline__ float exp_xla(float x) {
    x = fminf(x, 88.3762626647950f);
    x = fmaxf(x, -88.3762626647949f);
    float fx = floorf(__fmaf_rn(x, 1.44269504088896341f, 0.5f));
    float tmp = __fmul_rn(0.693359375f, fx);
    float z   = __fmul_rn(-2.12194440e-4f, fx);
    float r   = __fsub_rn(x, tmp);
    r = __fsub_rn(r, z);
    float zz = __fmul_rn(r, r);
    float y = __fmaf_rn(r, 1.9875691500E-4f, 1.3981999507E-3f);
    y = __fmaf_rn(y, r, 8.3334519073E-3f);
    y = __fmaf_rn(y, r, 4.1665795894E-2f);
    y = __fmaf_rn(y, r, 1.6666665459E-1f);
    y = __fmaf_rn(y, r, 5.0000001201E-1f);
    y = __fmaf_rn(y, zz, r);
    y = __fadd_rn(y, 1.0f);
    int emm0 = (((int)fx) + 127) << 23;
    return __fmul_rn(y, __int_as_float(emm0));
}

// ------------------------------------------------------------ prep
__global__ void k_prep_items(const float* __restrict__ emb) {
    int w = (blockIdx.x * blockDim.x + threadIdx.x) >> 5;
    int lane = threadIdx.x & 31;
    if (w >= NIT) return;
    const float* src = emb + (size_t)(w + 1) * D;
    float* dst = g_items + (size_t)w * DP;
    float ss = 0.f;
    for (int k = lane; k < DP; k += 32) {
        float v = (k < D) ? src[k] : 0.f;
        dst[k] = v;
        ss += v * v;
    }
    #pragma unroll
    for (int o = 16; o; o >>= 1) ss += __shfl_xor_sync(0xffffffffu, ss, o);
    if (lane == 0) g_invnorm[w] = 1.f / fmaxf(sqrtf(ss), 1e-12f);
}

__global__ void k_samp(const float* __restrict__ emb,
                       const int* __restrict__ viewed,
                       const int* __restrict__ bought) {
    int w = (blockIdx.x * blockDim.x + threadIdx.x) >> 5;
    int lane = threadIdx.x & 31;
    if (w >= NROWS) return;
    int idx = (w < NROWS / 2) ? viewed[w] : bought[w - NROWS / 2];
    const float* src = emb + (size_t)idx * D;
    float* dst = g_samp + (size_t)w * DP;
    for (int k = lane; k < DP; k += 32) dst[k] = (k < D) ? src[k] : 0.f;
}

__global__ void k_wt(const float* __restrict__ W) {
    int g = blockIdx.x * blockDim.x + threadIdx.x;
    if (g >= D * DP) return;
    int j = g / DP, d = g % DP;
    g_wt[g] = (d < D) ? W[d * D + j] : 0.f;
}

// ------------------------------------------------------------ SGEMM C = A * B^T
// Sequential-k fp32 fma accumulation per output element (Eigen gebp order).
// Packed fma.rn.f32x2 pairs adjacent j columns: each lane of the pair is an
// independent IEEE fp32 fma, so every C[i][j]'s k-chain is bit-identical to
// the scalar version.
__global__ void __launch_bounds__(256, 2) sgemm_nt(
    const float* __restrict__ A, int lda,
    const float* __restrict__ Bm, int ldb,
    float* __restrict__ C, int ldc,
    int M, int N, int K)
{
    __shared__ float As[2][8][128];
    __shared__ float Bs[2][8][128];
    int tid = threadIdx.x;
    int bm = blockIdx.y << 7, bn = blockIdx.x << 7;
    int lrow = tid >> 1;
    int lk = (tid & 1) << 2;
    const float* Ap = A + (size_t)(bm + lrow) * lda + lk;
    const float* Bp = Bm + (size_t)(bn + lrow) * ldb + lk;
    bool avld = (bm + lrow) < M;
    bool bvld = (bn + lrow) < N;
    float4 za = make_float4(0.f, 0.f, 0.f, 0.f);
    float4 ra = avld ? *(const float4*)Ap : za;
    float4 rb = bvld ? *(const float4*)Bp : za;
    As[0][lk + 0][lrow] = ra.x; As[0][lk + 1][lrow] = ra.y;
    As[0][lk + 2][lrow] = ra.z; As[0][lk + 3][lrow] = ra.w;
    Bs[0][lk + 0][lrow] = rb.x; Bs[0][lk + 1][lrow] = rb.y;
    Bs[0][lk + 2][lrow] = rb.z; Bs[0][lk + 3][lrow] = rb.w;
    __syncthreads();
    unsigned long long acc2[8][4];
    #pragma unroll
    for (int i = 0; i < 8; i++)
        #pragma unroll
        for (int t = 0; t < 4; t++) acc2[i][t] = 0ull;
    int ty = tid >> 4, tx = tid & 15;
    int buf = 0;
    for (int k0 = 8; k0 <= K; k0 += 8) {
        float4 na = za, nb = za;
        if (k0 < K) {
            na = avld ? *(const float4*)(Ap + k0) : za;
            nb = bvld ? *(const float4*)(Bp + k0) : za;
        }
        #pragma unroll
        for (int kk = 0; kk < 8; kk++) {
            float af[8];
            *(float4*)(af)     = *(const float4*)(&As[buf][kk][ty << 3]);
            *(float4*)(af + 4) = *(const float4*)(&As[buf][kk][(ty << 3) + 4]);
            ulonglong2 b01 = *(const ulonglong2*)(&Bs[buf][kk][tx << 3]);
            ulonglong2 b23 = *(const ulonglong2*)(&Bs[buf][kk][(tx << 3) + 4]);
            unsigned long long bb[4];
            bb[0] = b01.x; bb[1] = b01.y; bb[2] = b23.x; bb[3] = b23.y;
            unsigned long long aa[8];
            #pragma unroll
            for (int i = 0; i < 8; i++) aa[i] = pack_dup(af[i]);
            #pragma unroll
            for (int i = 0; i < 8; i++)
                #pragma unroll
                for (int t = 0; t < 4; t++)
                    acc2[i][t] = fma2(aa[i], bb[t], acc2[i][t]);
        }
        if (k0 < K) {
            buf ^= 1;
            As[buf][lk + 0][lrow] = na.x; As[buf][lk + 1][lrow] = na.y;
            As[buf][lk + 2][lrow] = na.z; As[buf][lk + 3][lrow] = na.w;
            Bs[buf][lk + 0][lrow] = nb.x; Bs[buf][lk + 1][lrow] = nb.y;
            Bs[buf][lk + 2][lrow] = nb.z; Bs[buf][lk + 3][lrow] = nb.w;
            __syncthreads();
        }
    }
    #pragma unroll
    for (int i = 0; i < 8; i++) {
        int m = bm + (ty << 3) + i;
        if (m >= M) continue;
        float* crow = C + (size_t)m * ldc + bn + (tx << 3);
        int ncol = bn + (tx << 3);
        float cv[8];
        #pragma unroll
        for (int t = 0; t < 4; t++) unpack2(acc2[i][t], cv[2 * t], cv[2 * t + 1]);
        #pragma unroll
        for (int j = 0; j < 8; j++)
            if (ncol + j < N) crow[j] = cv[j];
    }
}

// ------------------------------------------------------------ session MLP
__global__ void __launch_bounds__(320) k_sess(
    const float* __restrict__ emb, const float* __restrict__ posw,
    const float* __restrict__ w1, const float* __restrict__ w2,
    const float* __restrict__ glu1w, const float* __restrict__ glu1b,
    const float* __restrict__ glu2w, const float* __restrict__ mapd,
    const int* __restrict__ inputs, const int* __restrict__ masks,
    float* __restrict__ out)
{
    __shared__ float h[LL * D];
    __shared__ float nh1[D];
    __shared__ float hs[D];
    __shared__ float g2[D];
    __shared__ float sessv[D];
    __shared__ float red[320];
    __shared__ float beta[LL];
    __shared__ float mm[LL];
    int b = blockIdx.x, tid = threadIdx.x;
    if (tid < LL) mm[tid] = (float)masks[b * LL + tid];
    __syncthreads();
    if (tid < D) {
        float cnt = 0.f;
        for (int l = 0; l < LL; l++) {
            int idx = inputs[b * LL + l];
            h[l * D + tid] = (idx == 0) ? 0.f : emb[(size_t)idx * D + tid];
            cnt += mm[l];
        }
        float acc = 0.f;
        for (int l = 0; l < LL; l++) acc = fmaf(mm[l], h[l * D + tid], acc);
        hs[tid] = acc / cnt;
    }
    __syncthreads();
    if (tid < D) {
        float g = 0.f;
        for (int d = 0; d < D; d++) g = fmaf(hs[d], glu2w[d * D + tid], g);
        g2[tid] = g;
    }
    __syncthreads();
    for (int l = 0; l < LL; l++) {
        if (tid < D) {
            float a = 0.f;
            const float* pr = posw + l * D;
            for (int d = 0; d < D; d++) a = fmaf(pr[d], w1[d * D + tid], a);
            const float* hr = h + l * D;
            for (int d = 0; d < D; d++) a = fmaf(hr[d], w1[(D + d) * D + tid], a);
            nh1[tid] = tanhf(a);
        }
        __syncthreads();
        float val = 0.f;
        if (tid < D) {
            float a = glu1b[tid] + g2[tid];
            for (int d = 0; d < D; d++) a = fmaf(nh1[d], glu1w[d * D + tid], a);
            float sg = 1.f / (1.f + expf(-a));
            val = sg * w2[tid];
        }
        red[tid] = val;
        __syncthreads();
        if (tid < 64) red[tid] += red[tid + 256];
        __syncthreads();
        for (int st = 128; st > 0; st >>= 1) {
            if (tid < st) red[tid] += red[tid + st];
            __syncthreads();
        }
        if (tid == 0) beta[l] = red[0] * mm[l];
        __syncthreads();
    }
    float s2 = 0.f;
    if (tid < D) {
        float a = 0.f;
        for (int l = 0; l < LL; l++) a = fmaf(beta[l], h[l * D + tid], a);
        sessv[tid] = a;
        s2 = a * a;
    }
    red[tid] = s2;
    __syncthreads();
    if (tid < 64) red[tid] += red[tid + 256];
    __syncthreads();
    for (int st = 128; st > 0; st >>= 1) {
        if (tid < st) red[tid] += red[tid + st];
        __syncthreads();
    }
    float scale = 10.f / fmaxf(sqrtf(red[0]), 1e-12f);
    __syncthreads();
    if (tid < D) sessv[tid] = sessv[tid] * scale;
    __syncthreads();
    if (tid < D) {
        g_sess[b * D + tid] = sessv[tid];
        float a = 0.f;
        for (int d = 0; d < D; d++) a = fmaf(sessv[d], mapd[d * D + tid], a);
        out[O_SESSMAP + (size_t)b * D + tid] = a;
    }
}

// ------------------------------------------------------------ scores
__global__ void __launch_bounds__(256) k_scores(float* __restrict__ out) {
    __shared__ float ss[32 * D];
    int half = blockIdx.y;
    for (int i = threadIdx.x; i < 32 * D; i += 256) ss[i] = g_sess[half * 32 * D + i];
    __syncthreads();
    int n = blockIdx.x * 256 + threadIdx.x;
    if (n >= NIT) return;
    float acc[32];
    #pragma unroll
    for (int b = 0; b < 32; b++) acc[b] = 0.f;
    const float* gi = g_items + (size_t)n * DP;
    for (int d = 0; d < D; d += 4) {
        float4 v = *(const float4*)(gi + d);
        #pragma unroll
        for (int b = 0; b < 32; b++) {
            float4 s4 = *(const float4*)(ss + b * D + d);
            acc[b] = fmaf(v.x, s4.x, acc[b]);
            acc[b] = fmaf(v.y, s4.y, acc[b]);
            acc[b] = fmaf(v.z, s4.z, acc[b]);
            acc[b] = fmaf(v.w, s4.w, acc[b]);
        }
    }
    float inv = g_invnorm[n];
    #pragma unroll
    for (int b = 0; b < 32; b++)
        out[O_SCORES + (size_t)(half * 32 + b) * NIT + n] = acc[b] * inv;
}

// ------------------------------------------------------------ loss
__global__ void __launch_bounds__(256) k_loss1(const float* __restrict__ out,
                                               const int* __restrict__ targets) {
    __shared__ float red[256];
    int b = blockIdx.x, tid = threadIdx.x;
    const float* row = out + O_SCORES + (size_t)b * NIT;
    float mx = -3.4e38f;
    for (int n = tid; n < NIT; n += 256) mx = fmaxf(mx, row[n]);
    red[tid] = mx; __syncthreads();
    for (int s = 128; s; s >>= 1) { if (tid < s) red[tid] = fmaxf(red[tid], red[tid + s]); __syncthreads(); }
    float m = red[0]; __syncthreads();
    float se = 0.f;
    for (int n = tid; n < NIT; n += 256) se += expf(row[n] - m);
    red[tid] = se; __syncthreads();
    for (int s = 128; s; s >>= 1) { if (tid < s) red[tid] += red[tid + s]; __syncthreads(); }
    if (tid == 0) {
        int lbl = targets[b] - 1;
        g_red[b] = m + logf(red[0]) - row[lbl];
    }
}

__global__ void k_loss2(float* __restrict__ out) {
    __shared__ float red[64];
    int tid = threadIdx.x;
    red[tid] = g_red[tid];
    __syncthreads();
    for (int s = 32; s; s >>= 1) { if (tid < s) red[tid] += red[tid + s]; __syncthreads(); }
    if (tid == 0) out[0] = red[0] / 64.f;
}

// ------------------------------------------------------------ fused max+hist+Z+topk(sort)+gather — one block per row
__global__ void __launch_bounds__(TKT) k_topk(const int* __restrict__ slices,
                                              float* __restrict__ out,
                                              int rowoff) {
    __shared__ union {
        unsigned hist[4096];
        unsigned long long skey[2048];
    } u;
    __shared__ float cval[2048];
    __shared__ int cidx[2048];
    __shared__ int sel[100];
    __shared__ int slc[LL];
    __shared__ int s_T, s_n;
    __shared__ float rv[TKT];
    __shared__ float s_m, s_Z;
    int r = rowoff + blockIdx.x, tid = threadIdx.x;
    const float* row = g_sim + (size_t)r * SIMLD;
    const float4* rowv = (const float4*)row;
    for (int i = tid; i < 4096; i += TKT) u.hist[i] = 0;
    if (tid < LL) slc[tid] = slices[tid];
    if (tid == 0) s_n = 0;
    __syncthreads();
    // pass A: row max + logit histogram (9999 float4 + 3 scalar tail; elem 39999 is pad garbage)
    float mx = -3.4e38f;
    for (int i = tid; i < 9999; i += TKT) {
        float4 v4 = rowv[i];
        mx = fmaxf(fmaxf(mx, fmaxf(v4.x, v4.y)), fmaxf(v4.z, v4.w));
        unsigned ux = __float_as_uint(v4.x); ux = (ux & 0x80000000u) ? ~ux : (ux | 0x80000000u);
        unsigned uy = __float_as_uint(v4.y); uy = (uy & 0x80000000u) ? ~uy : (uy | 0x80000000u);
        unsigned uz = __float_as_uint(v4.z); uz = (uz & 0x80000000u) ? ~uz : (uz | 0x80000000u);
        unsigned uw = __float_as_uint(v4.w); uw = (uw & 0x80000000u) ? ~uw : (uw | 0x80000000u);
        atomicAdd(&u.hist[ux >> 20], 1u);
        atomicAdd(&u.hist[uy >> 20], 1u);
        atomicAdd(&u.hist[uz >> 20], 1u);
        atomicAdd(&u.hist[uw >> 20], 1u);
    }
    if (tid < 3) {
        float v = row[39996 + tid];
        mx = fmaxf(mx, v);
        unsigned uu = __float_as_uint(v); uu = (uu & 0x80000000u) ? ~uu : (uu | 0x80000000u);
        atomicAdd(&u.hist[uu >> 20], 1u);
    }
    rv[tid] = mx;
    __syncthreads();
    for (int s = TKT / 2; s; s >>= 1) { if (tid < s) rv[tid] = fmaxf(rv[tid], rv[tid + s]); __syncthreads(); }
    if (tid == 0) {
        s_m = rv[0];
        int cum = 0, T = 0;
        for (int bb = 4095; bb >= 0; bb--) { cum += (int)u.hist[bb]; if (cum >= 160) { T = bb; break; } }
        s_T = T;
    }
    __syncthreads();
    unsigned T = (unsigned)s_T;
    float m = s_m;
    // pass B: Z (exp_xla; Z bits ranking-invariant) + candidate collection
    float zacc = 0.f;
    for (int i = tid; i < 9999; i += TKT) {
        float4 v4 = rowv[i];
        zacc += exp_xla(v4.x - m); zacc += exp_xla(v4.y - m);
        zacc += exp_xla(v4.z - m); zacc += exp_xla(v4.w - m);
        #pragma unroll
        for (int c = 0; c < 4; c++) {
            float v = (c == 0) ? v4.x : (c == 1) ? v4.y : (c == 2) ? v4.z : v4.w;
            unsigned uu = __float_as_uint(v); uu = (uu & 0x80000000u) ? ~uu : (uu | 0x80000000u);
            if ((uu >> 20) >= T) {
                int p = atomicAdd(&s_n, 1);
                if (p < 2048) { cval[p] = v; cidx[p] = 4 * i + c; }
            }
        }
    }
    if (tid < 3) {
        float v = row[39996 + tid];
        zacc += exp_xla(v - m);
        unsigned uu = __float_as_uint(v); uu = (uu & 0x80000000u) ? ~uu : (uu | 0x80000000u);
        if ((uu >> 20) >= T) {
            int p = atomicAdd(&s_n, 1);
            if (p < 2048) { cval[p] = v; cidx[p] = 39996 + tid; }
        }
    }
    rv[tid] = zacc;
    __syncthreads();
    for (int s = TKT / 2; s; s >>= 1) { if (tid < s) rv[tid] += rv[tid + s]; __syncthreads(); }
    if (tid == 0) s_Z = rv[0];
    __syncthreads();
    int nc = min(s_n, 2048);
    float Z = s_Z;
    int n = 128;
    while (n < nc) n <<= 1;
    // build sort keys: (p_bits << 24) | (0xFFFFFF - idx)  — hist is dead, alias as skey
    for (int p = tid; p < n; p += TKT) {
        if (p < nc) {
            float e = exp_xla(__fsub_rn(cval[p], m));
            float pr = __fdiv_rn(e, Z);
            u.skey[p] = ((unsigned long long)__float_as_uint(pr) << 24)
                      | (unsigned)(0xFFFFFF - cidx[p]);
        } else {
            u.skey[p] = 0ull;
        }
    }
    __syncthreads();
    // bitonic sort descending, n elements
    for (int k2 = 2; k2 <= n; k2 <<= 1) {
        for (int j = k2 >> 1; j > 0; j >>= 1) {
            for (int i = tid; i < n; i += TKT) {
                int l = i ^ j;
                if (l > i) {
                    unsigned long long a = u.skey[i], b = u.skey[l];
                    bool up = ((i & k2) == 0);
                    if (up ? (a < b) : (a > b)) { u.skey[i] = b; u.skey[l] = a; }
                }
            }
            __syncthreads();
        }
    }
    if (tid < 100)
        sel[tid] = 0xFFFFFF - (int)(u.skey[tid] & 0xFFFFFFull);
    __syncthreads();
    size_t base = (r < NROWS / 2) ? (size_t)O_SUB : (size_t)O_COMP;
    int rr = (r < NROWS / 2) ? r : r - NROWS / 2;
    int b = rr / 100, l = (rr % 100) / 5, s = rr % 5;
    base += ((size_t)((b * LL + l) * 100 + s * LL)) * D;
    for (int i = tid; i < LL * D; i += TKT) {
        int e = i / D, d = i % D;
        int idx = sel[slc[e]];
        out[base + (size_t)e * D + d] = g_mapped[(size_t)idx * D + d];
    }
}

// ------------------------------------------------------------ launch (fork-join dual-stream capture)
extern "C" void kernel_launch(void* const* d_in, const int* in_sizes, int n_in,
                              void* d_out, int out_size) {
    const float* emb    = (const float*)d_in[0];
    const float* posw   = (const float*)d_in[1];
    const float* w1     = (const float*)d_in[2];
    const float* w2     = (const float*)d_in[3];
    const float* glu1w  = (const float*)d_in[4];
    const float* glu1b  = (const float*)d_in[5];
    const float* glu2w  = (const float*)d_in[6];
    const float* mapd   = (const float*)d_in[7];
    const int*   inputs = (const int*)d_in[8];
    const int*   targets= (const int*)d_in[9];
    const int*   masks  = (const int*)d_in[10];
    const int*   viewed = (const int*)d_in[11];
    const int*   bought = (const int*)d_in[12];
    const int*   slices = (const int*)d_in[13];
    float* out = (float*)d_out;

    float* items_p; cudaGetSymbolAddress((void**)&items_p, g_items);
    float* samp_p;  cudaGetSymbolAddress((void**)&samp_p,  g_samp);
    float* wt_p;    cudaGetSymbolAddress((void**)&wt_p,    g_wt);
    float* map_p;   cudaGetSymbolAddress((void**)&map_p,   g_mapped);
    float* sim_p;   cudaGetSymbolAddress((void**)&sim_p,   g_sim);

    static cudaStream_t s1 = nullptr;
    static cudaEvent_t evStart, evPrep, evJoin, evChunk[NCHUNK];
    if (!s1) {
        cudaStreamCreateWithFlags(&s1, cudaStreamNonBlocking);
        cudaEventCreateWithFlags(&evStart, cudaEventDisableTiming);
        cudaEventCreateWithFlags(&evPrep,  cudaEventDisableTiming);
        cudaEventCreateWithFlags(&evJoin,  cudaEventDisableTiming);
        for (int i = 0; i < NCHUNK; i++)
            cudaEventCreateWithFlags(&evChunk[i], cudaEventDisableTiming);
    }

    // fork: s1 joins the capture via evStart
    cudaEventRecord(evStart, 0);
    cudaStreamWaitEvent(s1, evStart, 0);

    // stream 0: prep inputs for the big GEMM
    k_prep_items<<<(NIT + 7) / 8, 256>>>(emb);
    k_samp<<<(NROWS + 7) / 8, 256>>>(emb, viewed, bought);
    cudaEventRecord(evPrep, 0);

    // stream 1: everything independent of the sim GEMM
    k_wt<<<(D * DP + 255) / 256, 256, 0, s1>>>(mapd);
    k_sess<<<BB, 320, 0, s1>>>(emb, posw, w1, w2, glu1w, glu1b, glu2w, mapd, inputs, masks, out);
    cudaStreamWaitEvent(s1, evPrep, 0);
    {   // mapped_all = all_item @ map_dense
        dim3 g((D + 127) / 128, (NIT + 127) / 128);
        sgemm_nt<<<g, 256, 0, s1>>>(items_p, DP, wt_p, DP, map_p, D, NIT, D, DP);
    }
    {
        dim3 g((NIT + 255) / 256, 2);
        k_scores<<<g, 256, 0, s1>>>(out);
    }
    k_loss1<<<BB, 256, 0, s1>>>(out, targets);
    k_loss2<<<1, 64, 0, s1>>>(out);

    // stream 0: sim GEMM in row chunks (bit-identical arithmetic; partitioned grid)
    for (int c = 0; c < NCHUNK; c++) {
        dim3 g((NIT + 127) / 128, CROWS / 128);
        sgemm_nt<<<g, 256>>>(samp_p + (size_t)c * CROWS * DP, DP,
                             items_p, DP,
                             sim_p + (size_t)c * CROWS * SIMLD, SIMLD,
                             CROWS, NIT, DP);
        cudaEventRecord(evChunk[c], 0);
    }

    // stream 1: fused znorm+topk+gather per chunk, overlapped with later GEMM chunks
    for (int c = 0; c < NCHUNK; c++) {
        cudaStreamWaitEvent(s1, evChunk[c], 0);
        k_topk<<<CROWS, TKT, 0, s1>>>(slices, out, c * CROWS);
    }

    // join back into the capture stream
    cudaEventRecord(evJoin, s1);
    cudaStreamWaitEvent(0, evJoin, 0);
}